// round 8
// baseline (speedup 1.0000x reference)
#include <cuda_runtime.h>
#include <math.h>

#define RESX   128
#define NVOX   (RESX*RESX*RESX)
#define NRAYS  1024
#define NS     891

#define ACT_SHIFT (-4.5951198501345898f)

// ---------------- global scratch ----------------
__device__ float g_norm[3*NVOX];
__device__ float g_w[NRAYS*NS];
__device__ float g_T[NRAYS];
__device__ float g_tmin[NRAYS];
__device__ float g_invn[NRAYS];
__device__ int   g_sstart[NRAYS];
__device__ int   g_scnt[NRAYS];
__device__ int   g_base[NRAYS+1];
__device__ int   g_total;
__device__ int   g_work;

// ---------------------------------------------------------------------------
// packed fp32x2 helpers
// ---------------------------------------------------------------------------
typedef unsigned long long u64;
__device__ __forceinline__ u64 f2pack(float lo, float hi){
    u64 r; asm("mov.b64 %0,{%1,%2};" : "=l"(r) : "f"(lo), "f"(hi)); return r;
}
__device__ __forceinline__ void f2unpack(u64 v, float& lo, float& hi){
    asm("mov.b64 {%0,%1},%2;" : "=f"(lo), "=f"(hi) : "l"(v));
}
__device__ __forceinline__ u64 ffma2(u64 a, u64 b, u64 c){
    u64 d; asm("fma.rn.f32x2 %0,%1,%2,%3;" : "=l"(d) : "l"(a), "l"(b), "l"(c)); return d;
}

__device__ __forceinline__ void tri_setup(float px, float py, float pz,
                                          int* off, float* w)
{
    float ga = (px + 1.f)*0.5f*127.f;
    float gb = (py + 1.f)*0.5f*127.f;
    float gc = (pz + 1.f)*0.5f*127.f;
    float fa0 = floorf(ga), fb0 = floorf(gb), fc0 = floorf(gc);
    float fa = ga - fa0, fb = gb - fb0, fc = gc - fc0;
    int a0 = min(max((int)fa0, 0), 127);
    int b0 = min(max((int)fb0, 0), 127);
    int c0 = min(max((int)fc0, 0), 127);
    int a1 = min(a0+1, 127), b1 = min(b0+1, 127), c1 = min(c0+1, 127);
    int A0 = a0*16384, A1 = a1*16384, B0 = b0*128, B1 = b1*128;
    off[0]=A0+B0+c0; off[1]=A0+B0+c1; off[2]=A0+B1+c0; off[3]=A0+B1+c1;
    off[4]=A1+B0+c0; off[5]=A1+B0+c1; off[6]=A1+B1+c0; off[7]=A1+B1+c1;
    float wa0 = 1.f-fa, wb0 = 1.f-fb, wc0 = 1.f-fc;
    w[0]=wa0*wb0*wc0; w[1]=wa0*wb0*fc; w[2]=wa0*fb*wc0; w[3]=wa0*fb*fc;
    w[4]=fa*wb0*wc0;  w[5]=fa*wb0*fc;  w[6]=fa*fb*wc0;  w[7]=fa*fb*fc;
}

// ---------------------------------------------------------------------------
// Kernel 1: FUSED conv (blocks 0..2047, f32x2 with PRE-PACKED kernel taps)
// + prep (2048..3071, parallel transmittance scan).
// ---------------------------------------------------------------------------
#define CONV_BLOCKS 2048
__global__ void __launch_bounds__(256) fused_kernel(
    const float* __restrict__ dens, const float* __restrict__ kern,
    const float* __restrict__ ro,   const float* __restrict__ rdv)
{
    __shared__ float smem_u[8*12*36];     // conv: tile; prep: aw (891)
    __shared__ u64   skp[375];            // conv only: pre-packed (k,k)
    __shared__ float s_wprod[8];
    __shared__ int s_min, s_max;

    if (blockIdx.x < CONV_BLOCKS){
        // ----------------- conv path -----------------
        float* tile = smem_u;
        int bid = blockIdx.x;
        int tc = threadIdx.x & 31;
        int tb = (threadIdx.x >> 5);
        int tid = threadIdx.x;
        int c0 = (bid & 3)*32;
        int b0 = ((bid >> 2) & 15)*8;
        int a0 = (bid >> 6)*4;

        for (int i=tid; i<375; i+=256){
            float k = kern[i];
            skp[i] = f2pack(k, k);
        }
        for (int i=tid; i<8*12*36; i+=256){
            int ic = i % 36; int r = i / 36; int ib = r % 12; int ia = r / 12;
            int ga = a0 - 2 + ia, gb = b0 - 2 + ib, gc = c0 - 2 + ic;
            float v = 0.f;
            if ((unsigned)ga < 128u && (unsigned)gb < 128u && (unsigned)gc < 128u)
                v = dens[(ga*128 + gb)*128 + gc];
            tile[i] = v;
        }
        __syncthreads();

        u64 s0p[2]={0,0}, s1p[2]={0,0}, s2p[2]={0,0};
        for (int db=0; db<5; db++){
            for (int dc=0; dc<5; dc++){
                float tv[8];
                #pragma unroll
                for (int ia=0; ia<8; ia++)
                    tv[ia] = tile[(ia*12 + tb + db)*36 + tc + dc];
                u64 p[7];
                #pragma unroll
                for (int i=0; i<7; i++) p[i] = f2pack(tv[i], tv[i+1]);
                #pragma unroll
                for (int da=0; da<5; da++){
                    u64 kp0 = skp[0*125 + da*25 + db*5 + dc];
                    u64 kp1 = skp[1*125 + da*25 + db*5 + dc];
                    u64 kp2 = skp[2*125 + da*25 + db*5 + dc];
                    s0p[0] = ffma2(kp0, p[da],   s0p[0]);
                    s0p[1] = ffma2(kp0, p[da+2], s0p[1]);
                    s1p[0] = ffma2(kp1, p[da],   s1p[0]);
                    s1p[1] = ffma2(kp1, p[da+2], s1p[1]);
                    s2p[0] = ffma2(kp2, p[da],   s2p[0]);
                    s2p[1] = ffma2(kp2, p[da+2], s2p[1]);
                }
            }
        }
        float s0[4], s1[4], s2[4];
        f2unpack(s0p[0], s0[0], s0[1]); f2unpack(s0p[1], s0[2], s0[3]);
        f2unpack(s1p[0], s1[0], s1[1]); f2unpack(s1p[1], s1[2], s1[3]);
        f2unpack(s2p[0], s2[0], s2[1]); f2unpack(s2p[1], s2[2], s2[3]);
        #pragma unroll
        for (int v=0; v<4; v++){
            int idx = ((a0+v)*128 + (b0+tb))*128 + (c0+tc);
            float n0 = s0[v], n1 = s1[v], n2 = s2[v];
            float len = sqrtf(n0*n0 + n1*n1 + n2*n2);
            float inv = -1.f / fmaxf(len, 1e-12f);
            g_norm[idx]          = n0*inv;
            g_norm[NVOX + idx]   = n1*inv;
            g_norm[2*NVOX + idx] = n2*inv;
        }
    } else {
        // ----------------- prep path -----------------
        float* aw = smem_u;
        int tid = threadIdx.x;
        int lane = tid & 31, wid = tid >> 5;
        int rid = blockIdx.x - CONV_BLOCKS;
        if (tid == 0){ s_min = 0x7fffffff; s_max = -1; }
        __syncthreads();

        float ox = ro[rid*3+0], oy = ro[rid*3+1], oz = ro[rid*3+2];
        float dx = rdv[rid*3+0], dy = rdv[rid*3+1], dz = rdv[rid*3+2];

        float vecx = (dx == 0.f) ? 1e-6f : dx;
        float vecy = (dy == 0.f) ? 1e-6f : dy;
        float vecz = (dz == 0.f) ? 1e-6f : dz;
        float rax = ( 1.f - ox)/vecx, rbx = (-1.f - ox)/vecx;
        float ray_ = ( 1.f - oy)/vecy, rby = (-1.f - oy)/vecy;
        float raz = ( 1.f - oz)/vecz, rbz = (-1.f - oz)/vecz;
        float tmin = fmaxf(fmaxf(fminf(rax,rbx), fminf(ray_,rby)), fminf(raz,rbz));
        tmin = fminf(fmaxf(tmin, 0.2f), 3.0f);
        float tmax = fminf(fminf(fmaxf(rax,rbx), fmaxf(ray_,rby)), fmaxf(raz,rbz));
        tmax = fminf(fmaxf(tmax, 0.2f), 3.0f);
        bool maskray = (tmax <= tmin);
        float invn = 1.f / sqrtf(dx*dx + dy*dy + dz*dz);

        int lmin = 0x7fffffff, lmax = -1;
        for (int s=tid; s<NS; s+=256){
            float t  = tmin + (0.0078125f * (float)s) * invn;
            float px = fmaf(dx, t, ox), py = fmaf(dy, t, oy), pz = fmaf(dz, t, oz);
            bool in = (!maskray) &&
                      !(px < -1.f || px > 1.f || py < -1.f || py > 1.f || pz < -1.f || pz > 1.f);
            float a = 0.f;
            if (in){
                int off[8]; float wc[8];
                tri_setup(px, py, pz, off, wc);
                float l0 = 0.f;
                #pragma unroll
                for (int k=0; k<8; k++) l0 = fmaf(wc[k], __ldg(dens + off[k]), l0);
                float xs = l0 + ACT_SHIFT;
                float sp = fmaxf(xs, 0.f) + log1pf(expf(-fabsf(xs)));
                a = 1.f - expf(-sp*0.5f);
                lmin = min(lmin, s); lmax = max(lmax, s);
            }
            aw[s] = a;
        }
        if (lmax >= 0){ atomicMin(&s_min, lmin); atomicMax(&s_max, lmax); }
        __syncthreads();

        // parallel transmittance scan: 4 contiguous samples / thread
        int base4 = tid*4;
        float lp = 1.f;
        #pragma unroll
        for (int j=0; j<4; j++){
            int s = base4 + j;
            if (s < NS) lp *= fmaxf(1.f - aw[s], 1e-10f);
        }
        float v = lp;
        #pragma unroll
        for (int o=1; o<32; o<<=1){
            float n = __shfl_up_sync(0xffffffffu, v, o);
            if (lane >= o) v *= n;
        }
        if (lane == 31) s_wprod[wid] = v;
        __syncthreads();
        float warp_excl = 1.f;
        #pragma unroll
        for (int wj=0; wj<8; wj++)
            if (wj < wid) warp_excl *= s_wprod[wj];
        float vexcl = __shfl_up_sync(0xffffffffu, v, 1);
        if (lane == 0) vexcl = 1.f;
        float T = warp_excl * vexcl;

        int smn = s_min, smx = s_max;
        #pragma unroll
        for (int j=0; j<4; j++){
            int s = base4 + j;
            if (s < NS){
                float a = aw[s];
                if (s >= smn && s <= smx)
                    g_w[rid*NS + s] = a * T;
                T *= fmaxf(1.f - a, 1e-10f);
            }
        }

        if (tid == 0){
            float Tall = 1.f;
            #pragma unroll
            for (int wj=0; wj<8; wj++) Tall *= s_wprod[wj];
            g_T[rid]    = Tall;
            g_tmin[rid] = tmin;
            g_invn[rid] = invn;
            int cnt = (smx >= smn) ? (smx - smn + 1) : 0;
            g_sstart[rid] = (cnt > 0) ? smn : 0;
            g_scnt[rid]   = cnt;
        }
    }
}

// ---------------------------------------------------------------------------
// Kernel 2: exclusive scan + work reset + out init (out = T * BG, BG=1).
// ---------------------------------------------------------------------------
__global__ void __launch_bounds__(1024) scan_kernel(float* __restrict__ out)
{
    __shared__ int wsum[32];
    int t = threadIdx.x;
    int lane = t & 31, wid = t >> 5;
    int v = g_scnt[t];
    #pragma unroll
    for (int o=1; o<32; o<<=1){
        int n = __shfl_up_sync(0xffffffffu, v, o);
        if (lane >= o) v += n;
    }
    if (lane == 31) wsum[wid] = v;
    __syncthreads();
    if (wid == 0){
        int w = wsum[lane];
        #pragma unroll
        for (int o=1; o<32; o<<=1){
            int n = __shfl_up_sync(0xffffffffu, w, o);
            if (lane >= o) w += n;
        }
        wsum[lane] = w;
    }
    __syncthreads();
    if (wid > 0) v += wsum[wid-1];
    g_base[t+1] = v;
    if (t == 0){ g_base[0] = 0; g_work = 0; }
    if (t == 1023) g_total = v;

    float Tf = g_T[t];
    out[t*3+0] = Tf;
    out[t*3+1] = Tf;
    out[t*3+2] = Tf;
}

// ---------------------------------------------------------------------------
// Kernel 3: pair-split MLP, results accumulated straight into out via RED.ADD.
// ---------------------------------------------------------------------------
#define OFF_W0    0
#define OFF_W1    3464
#define OFF_W2    7568
#define OFF_W3    11672
#define OFF_B0    11864
#define OFF_B1    11928
#define OFF_B2    11992
#define OFF_B3    12056
#define OFF_BASE  12060
#define OFF_STAGE 13088
#define MLP_NTH   384
#define SH_FLOATS (OFF_STAGE + (MLP_NTH/2)*130)
#define SMEM_MLP  (SH_FLOATS*4)
#define MLP_BLOCKS 148

__device__ __forceinline__ void gemv_pair(u64* hA, u64* hB,
                                          const float* wbase,
                                          const float* fp, int R)
{
    for (int i=0; i<R; i++){
        float2 vp = *(const float2*)(fp + i*2);
        u64 vvA = f2pack(vp.x, vp.x);
        u64 vvB = f2pack(vp.y, vp.y);
        const ulonglong2* wr = (const ulonglong2*)(wbase + i*32);
        #pragma unroll
        for (int k=0; k<8; k++){
            ulonglong2 w2 = wr[k];
            hA[2*k]   = ffma2(vvA, w2.x, hA[2*k]);
            hA[2*k+1] = ffma2(vvA, w2.y, hA[2*k+1]);
            hB[2*k]   = ffma2(vvB, w2.x, hB[2*k]);
            hB[2*k+1] = ffma2(vvB, w2.y, hB[2*k+1]);
        }
    }
}

__device__ __forceinline__ void bias_init(u64* hA, u64* hB,
                                          const float* bias, int hf)
{
    const u64* bp = (const u64*)bias;
    #pragma unroll
    for (int k=0; k<16; k++){ u64 bb = bp[hf*16 + k]; hA[k]=bb; hB[k]=bb; }
}

__device__ __forceinline__ void relu_stage(const u64* hA, const u64* hB,
                                           float* fp, int hf)
{
    #pragma unroll
    for (int k=0; k<16; k++){
        float a0,a1,b0,b1;
        f2unpack(hA[k], a0, a1);
        f2unpack(hB[k], b0, b1);
        a0 = fmaxf(a0,0.f); a1 = fmaxf(a1,0.f);
        b0 = fmaxf(b0,0.f); b1 = fmaxf(b1,0.f);
        int n = hf*32 + 2*k;
        *(float2*)(fp + n*2)     = make_float2(a0, b0);
        *(float2*)(fp + n*2 + 2) = make_float2(a1, b1);
    }
}

__global__ void __launch_bounds__(MLP_NTH, 1) mlp_kernel(
    const float* __restrict__ ro,  const float* __restrict__ rdv,
    const float* __restrict__ vdv, const float* __restrict__ grid,
    const float* __restrict__ w0,  const float* __restrict__ b0,
    const float* __restrict__ w1,  const float* __restrict__ b1,
    const float* __restrict__ w2,  const float* __restrict__ b2,
    const float* __restrict__ w3,  const float* __restrict__ b3,
    float* __restrict__ out)
{
    extern __shared__ float sh[];
    int tid  = threadIdx.x;
    int lane = tid & 31;
    int hf   = tid & 1;
    int pg   = tid >> 1;
    int* sbase = (int*)(sh + OFF_BASE);

    for (int i=tid; i<54*64; i+=MLP_NTH){
        int r = i>>6, j = i&63;
        int dst = (j<32) ? (r*32+j) : (54*32+4 + r*32 + (j-32));
        sh[OFF_W0+dst] = w0[i];
    }
    for (int i=tid; i<64*64; i+=MLP_NTH){
        int r = i>>6, j = i&63;
        int dst = (j<32) ? (r*32+j) : (64*32+4 + r*32 + (j-32));
        sh[OFF_W1+dst] = w1[i];
        sh[OFF_W2+dst] = w2[i];
    }
    for (int i=tid; i<192; i+=MLP_NTH) sh[OFF_W3+i] = w3[i];
    for (int i=tid; i<64;  i+=MLP_NTH){
        sh[OFF_B0+i]=b0[i]; sh[OFF_B1+i]=b1[i]; sh[OFF_B2+i]=b2[i];
    }
    if (tid < 3) sh[OFF_B3+tid] = b3[tid];
    for (int i=tid; i<NRAYS+1; i+=MLP_NTH) sbase[i] = g_base[i];
    __syncthreads();

    int total   = g_total;
    int nchunks = (total + 31) >> 5;
    float* fp = sh + OFF_STAGE + pg*130;
    const float* wl0 = sh + OFF_W0 + hf*(54*32+4);
    const float* wl1 = sh + OFF_W1 + hf*(64*32+4);
    const float* wl2 = sh + OFF_W2 + hf*(64*32+4);

    while (true){
        int chunk = 0;
        if (lane == 0) chunk = atomicAdd(&g_work, 1);
        chunk = __shfl_sync(0xffffffffu, chunk, 0);
        if (chunk >= nchunks) break;
        int e = chunk*32 + lane;
        bool valid = (e < total);
        int ec = valid ? e : (total - 1);

        int lo = 0, hi = NRAYS;
        while (hi - lo > 1){
            int mid = (lo + hi) >> 1;
            if (sbase[mid] <= ec) lo = mid; else hi = mid;
        }
        int ray = lo;
        int s = g_sstart[ray] + (ec - sbase[ray]);

        float ox = __ldg(ro+ray*3+0), oy = __ldg(ro+ray*3+1), oz = __ldg(ro+ray*3+2);
        float dx = __ldg(rdv+ray*3+0), dy = __ldg(rdv+ray*3+1), dz = __ldg(rdv+ray*3+2);
        float vx = __ldg(vdv+ray*3+0), vy = __ldg(vdv+ray*3+1), vz = __ldg(vdv+ray*3+2);
        float tmin = __ldg(&g_tmin[ray]);
        float invn = __ldg(&g_invn[ray]);
        float wgt  = __ldg(&g_w[ray*NS + s]);

        float t  = tmin + (0.0078125f * (float)s) * invn;
        float px = fmaf(dx, t, ox), py = fmaf(dy, t, oy), pz = fmaf(dz, t, oz);

        int off[8]; float wc[8];
        tri_setup(px, py, pz, off, wc);

        float nvx[8], nvy[8], nvz[8];
        #pragma unroll
        for (int k=0; k<8; k++){
            nvx[k] = __ldg(g_norm + off[k]);
            nvy[k] = __ldg(g_norm + NVOX + off[k]);
            nvz[k] = __ldg(g_norm + 2*NVOX + off[k]);
        }

        for (int ch=1; ch<=15; ++ch){
            const float* gp = grid + ch*NVOX;
            float v = 0.f;
            #pragma unroll
            for (int k=0; k<8; k++) v = fmaf(wc[k], __ldg(gp + off[k]), v);
            fp[(ch-1)*2 + hf] = v;
        }

        float nsx = 0.f, nsy = 0.f, nsz = 0.f;
        #pragma unroll
        for (int k=0; k<8; k++){
            nsx = fmaf(wc[k], nvx[k], nsx);
            nsy = fmaf(wc[k], nvy[k], nsy);
            nsz = fmaf(wc[k], nvz[k], nsz);
        }
        float nl = sqrtf(nsx*nsx + nsy*nsy + nsz*nsz);
        float ninv = -1.f / fmaxf(nl, 1e-12f);
        nsx *= ninv; nsy *= ninv; nsz *= ninv;
        float dt  = -(vx*nsx + vy*nsy + vz*nsz);
        float rx = fmaf(2.f*dt, nsx, vx);
        float ry = fmaf(2.f*dt, nsy, vy);
        float rz = fmaf(2.f*dt, nsz, vz);
        fp[15*2 + hf] = rx;
        fp[16*2 + hf] = ry;
        fp[17*2 + hf] = rz;

        for (int f=0; f<6; ++f){
            float fr = (float)(1 << f);
            #pragma unroll
            for (int k3=0; k3<3; k3++){
                float ang = (k3==0 ? rx : (k3==1 ? ry : rz)) * fr;
                float kk = rintf(ang * 0.15915494309189535f);
                float r2 = fmaf(kk, -6.283185307179586f, ang);
                float sn, cs;
                sincosf(r2, &sn, &cs);
                fp[(18 + f*3 + k3)*2 + hf] = sn;
                fp[(36 + f*3 + k3)*2 + hf] = cs;
            }
        }
        __syncwarp();

        u64 hA[16], hB[16];
        bias_init(hA, hB, sh + OFF_B0, hf);
        gemv_pair(hA, hB, wl0, fp, 54);
        __syncwarp();
        relu_stage(hA, hB, fp, hf);
        __syncwarp();

        bias_init(hA, hB, sh + OFF_B1, hf);
        gemv_pair(hA, hB, wl1, fp, 64);
        __syncwarp();
        relu_stage(hA, hB, fp, hf);
        __syncwarp();

        bias_init(hA, hB, sh + OFF_B2, hf);
        gemv_pair(hA, hB, wl2, fp, 64);

        float pA0=0.f,pA1=0.f,pA2=0.f,pB0=0.f,pB1=0.f,pB2=0.f;
        #pragma unroll
        for (int k=0; k<16; k++){
            float a0,a1,b0v,b1v;
            f2unpack(hA[k], a0, a1);
            f2unpack(hB[k], b0v, b1v);
            a0 = fmaxf(a0,0.f); a1 = fmaxf(a1,0.f);
            b0v = fmaxf(b0v,0.f); b1v = fmaxf(b1v,0.f);
            int n0 = hf*32 + 2*k;
            float q00 = sh[OFF_W3 + n0*3 + 0];
            float q01 = sh[OFF_W3 + n0*3 + 1];
            float q02 = sh[OFF_W3 + n0*3 + 2];
            float q10 = sh[OFF_W3 + n0*3 + 3];
            float q11 = sh[OFF_W3 + n0*3 + 4];
            float q12 = sh[OFF_W3 + n0*3 + 5];
            pA0 = fmaf(a0,q00, fmaf(a1,q10, pA0));
            pA1 = fmaf(a0,q01, fmaf(a1,q11, pA1));
            pA2 = fmaf(a0,q02, fmaf(a1,q12, pA2));
            pB0 = fmaf(b0v,q00, fmaf(b1v,q10, pB0));
            pB1 = fmaf(b0v,q01, fmaf(b1v,q11, pB1));
            pB2 = fmaf(b0v,q02, fmaf(b1v,q12, pB2));
        }
        pA0 += __shfl_xor_sync(0xffffffffu, pA0, 1);
        pA1 += __shfl_xor_sync(0xffffffffu, pA1, 1);
        pA2 += __shfl_xor_sync(0xffffffffu, pA2, 1);
        pB0 += __shfl_xor_sync(0xffffffffu, pB0, 1);
        pB1 += __shfl_xor_sync(0xffffffffu, pB1, 1);
        pB2 += __shfl_xor_sync(0xffffffffu, pB2, 1);

        float c0s = (hf ? pB0 : pA0) + sh[OFF_B3+0];
        float c1s = (hf ? pB1 : pA1) + sh[OFF_B3+1];
        float c2s = (hf ? pB2 : pA2) + sh[OFF_B3+2];
        float col0 = 1.f / (1.f + expf(-c0s));
        float col1 = 1.f / (1.f + expf(-c1s));
        float col2 = 1.f / (1.f + expf(-c2s));
        if (valid){
            atomicAdd(&out[ray*3+0], wgt * col0);
            atomicAdd(&out[ray*3+1], wgt * col1);
            atomicAdd(&out[ray*3+2], wgt * col2);
        }
    }
}

extern "C" void kernel_launch(void* const* d_in, const int* in_sizes, int n_in,
                              void* d_out, int out_size)
{
    (void)in_sizes; (void)n_in; (void)out_size;
    const float* ro    = (const float*)d_in[0];
    const float* rd    = (const float*)d_in[1];
    const float* vd    = (const float*)d_in[2];
    const float* grid  = (const float*)d_in[3];
    const float* sobel = (const float*)d_in[4];
    const float* w0 = (const float*)d_in[5];
    const float* b0 = (const float*)d_in[6];
    const float* w1 = (const float*)d_in[7];
    const float* b1 = (const float*)d_in[8];
    const float* w2 = (const float*)d_in[9];
    const float* b2 = (const float*)d_in[10];
    const float* w3 = (const float*)d_in[11];
    const float* b3 = (const float*)d_in[12];
    float* out = (float*)d_out;

    fused_kernel<<<CONV_BLOCKS + NRAYS, 256>>>(grid, sobel, ro, rd);
    scan_kernel<<<1, 1024>>>(out);

    static int smem_set = 0;
    if (!smem_set){
        cudaFuncSetAttribute(mlp_kernel,
                             cudaFuncAttributeMaxDynamicSharedMemorySize, SMEM_MLP);
        smem_set = 1;
    }
    mlp_kernel<<<MLP_BLOCKS, MLP_NTH, SMEM_MLP>>>(ro, rd, vd, grid,
                                                  w0, b0, w1, b1, w2, b2, w3, b3, out);
}

// round 9
// speedup vs baseline: 1.0492x; 1.0492x over previous
#include <cuda_runtime.h>
#include <math.h>

#define RESX   128
#define NVOX   (RESX*RESX*RESX)
#define NRAYS  1024
#define NS     891

#define ACT_SHIFT (-4.5951198501345898f)

// ---------------- global scratch ----------------
__device__ float g_norm[3*NVOX];
__device__ float g_w[NRAYS*NS];
__device__ float g_T[NRAYS];
__device__ float g_tmin[NRAYS];
__device__ float g_invn[NRAYS];
__device__ int   g_sstart[NRAYS];
__device__ int   g_scnt[NRAYS];
__device__ int   g_base[NRAYS+1];
__device__ int   g_total;
__device__ int   g_work;

// ---------------------------------------------------------------------------
// packed fp32x2 helpers
// ---------------------------------------------------------------------------
typedef unsigned long long u64;
__device__ __forceinline__ u64 f2pack(float lo, float hi){
    u64 r; asm("mov.b64 %0,{%1,%2};" : "=l"(r) : "f"(lo), "f"(hi)); return r;
}
__device__ __forceinline__ void f2unpack(u64 v, float& lo, float& hi){
    asm("mov.b64 {%0,%1},%2;" : "=f"(lo), "=f"(hi) : "l"(v));
}
__device__ __forceinline__ u64 ffma2(u64 a, u64 b, u64 c){
    u64 d; asm("fma.rn.f32x2 %0,%1,%2,%3;" : "=l"(d) : "l"(a), "l"(b), "l"(c)); return d;
}

__device__ __forceinline__ void tri_setup(float px, float py, float pz,
                                          int* off, float* w)
{
    float ga = (px + 1.f)*0.5f*127.f;
    float gb = (py + 1.f)*0.5f*127.f;
    float gc = (pz + 1.f)*0.5f*127.f;
    float fa0 = floorf(ga), fb0 = floorf(gb), fc0 = floorf(gc);
    float fa = ga - fa0, fb = gb - fb0, fc = gc - fc0;
    int a0 = min(max((int)fa0, 0), 127);
    int b0 = min(max((int)fb0, 0), 127);
    int c0 = min(max((int)fc0, 0), 127);
    int a1 = min(a0+1, 127), b1 = min(b0+1, 127), c1 = min(c0+1, 127);
    int A0 = a0*16384, A1 = a1*16384, B0 = b0*128, B1 = b1*128;
    off[0]=A0+B0+c0; off[1]=A0+B0+c1; off[2]=A0+B1+c0; off[3]=A0+B1+c1;
    off[4]=A1+B0+c0; off[5]=A1+B0+c1; off[6]=A1+B1+c0; off[7]=A1+B1+c1;
    float wa0 = 1.f-fa, wb0 = 1.f-fb, wc0 = 1.f-fc;
    w[0]=wa0*wb0*wc0; w[1]=wa0*wb0*fc; w[2]=wa0*fb*wc0; w[3]=wa0*fb*fc;
    w[4]=fa*wb0*wc0;  w[5]=fa*wb0*fc;  w[6]=fa*fb*wc0;  w[7]=fa*fb*fc;
}

// ---------------------------------------------------------------------------
// Kernel 1: FUSED conv (blocks 0..2047, f32x2 with PRE-PACKED kernel taps)
// + prep (2048..3071, parallel transmittance scan).
// ---------------------------------------------------------------------------
#define CONV_BLOCKS 2048
__global__ void __launch_bounds__(256) fused_kernel(
    const float* __restrict__ dens, const float* __restrict__ kern,
    const float* __restrict__ ro,   const float* __restrict__ rdv)
{
    __shared__ float smem_u[8*12*36];     // conv: tile; prep: aw (891)
    __shared__ u64   skp[375];            // conv only: pre-packed (k,k)
    __shared__ float s_wprod[8];
    __shared__ int s_min, s_max;

    if (blockIdx.x < CONV_BLOCKS){
        // ----------------- conv path -----------------
        float* tile = smem_u;
        int bid = blockIdx.x;
        int tc = threadIdx.x & 31;
        int tb = (threadIdx.x >> 5);
        int tid = threadIdx.x;
        int c0 = (bid & 3)*32;
        int b0 = ((bid >> 2) & 15)*8;
        int a0 = (bid >> 6)*4;

        for (int i=tid; i<375; i+=256){
            float k = kern[i];
            skp[i] = f2pack(k, k);
        }
        for (int i=tid; i<8*12*36; i+=256){
            int ic = i % 36; int r = i / 36; int ib = r % 12; int ia = r / 12;
            int ga = a0 - 2 + ia, gb = b0 - 2 + ib, gc = c0 - 2 + ic;
            float v = 0.f;
            if ((unsigned)ga < 128u && (unsigned)gb < 128u && (unsigned)gc < 128u)
                v = dens[(ga*128 + gb)*128 + gc];
            tile[i] = v;
        }
        __syncthreads();

        u64 s0p[2]={0,0}, s1p[2]={0,0}, s2p[2]={0,0};
        for (int db=0; db<5; db++){
            for (int dc=0; dc<5; dc++){
                float tv[8];
                #pragma unroll
                for (int ia=0; ia<8; ia++)
                    tv[ia] = tile[(ia*12 + tb + db)*36 + tc + dc];
                u64 p[7];
                #pragma unroll
                for (int i=0; i<7; i++) p[i] = f2pack(tv[i], tv[i+1]);
                #pragma unroll
                for (int da=0; da<5; da++){
                    u64 kp0 = skp[0*125 + da*25 + db*5 + dc];
                    u64 kp1 = skp[1*125 + da*25 + db*5 + dc];
                    u64 kp2 = skp[2*125 + da*25 + db*5 + dc];
                    s0p[0] = ffma2(kp0, p[da],   s0p[0]);
                    s0p[1] = ffma2(kp0, p[da+2], s0p[1]);
                    s1p[0] = ffma2(kp1, p[da],   s1p[0]);
                    s1p[1] = ffma2(kp1, p[da+2], s1p[1]);
                    s2p[0] = ffma2(kp2, p[da],   s2p[0]);
                    s2p[1] = ffma2(kp2, p[da+2], s2p[1]);
                }
            }
        }
        float s0[4], s1[4], s2[4];
        f2unpack(s0p[0], s0[0], s0[1]); f2unpack(s0p[1], s0[2], s0[3]);
        f2unpack(s1p[0], s1[0], s1[1]); f2unpack(s1p[1], s1[2], s1[3]);
        f2unpack(s2p[0], s2[0], s2[1]); f2unpack(s2p[1], s2[2], s2[3]);
        #pragma unroll
        for (int v=0; v<4; v++){
            int idx = ((a0+v)*128 + (b0+tb))*128 + (c0+tc);
            float n0 = s0[v], n1 = s1[v], n2 = s2[v];
            float len = sqrtf(n0*n0 + n1*n1 + n2*n2);
            float inv = -1.f / fmaxf(len, 1e-12f);
            g_norm[idx]          = n0*inv;
            g_norm[NVOX + idx]   = n1*inv;
            g_norm[2*NVOX + idx] = n2*inv;
        }
    } else {
        // ----------------- prep path -----------------
        float* aw = smem_u;
        int tid = threadIdx.x;
        int lane = tid & 31, wid = tid >> 5;
        int rid = blockIdx.x - CONV_BLOCKS;
        if (tid == 0){ s_min = 0x7fffffff; s_max = -1; }
        __syncthreads();

        float ox = ro[rid*3+0], oy = ro[rid*3+1], oz = ro[rid*3+2];
        float dx = rdv[rid*3+0], dy = rdv[rid*3+1], dz = rdv[rid*3+2];

        float vecx = (dx == 0.f) ? 1e-6f : dx;
        float vecy = (dy == 0.f) ? 1e-6f : dy;
        float vecz = (dz == 0.f) ? 1e-6f : dz;
        float rax = ( 1.f - ox)/vecx, rbx = (-1.f - ox)/vecx;
        float ray_ = ( 1.f - oy)/vecy, rby = (-1.f - oy)/vecy;
        float raz = ( 1.f - oz)/vecz, rbz = (-1.f - oz)/vecz;
        float tmin = fmaxf(fmaxf(fminf(rax,rbx), fminf(ray_,rby)), fminf(raz,rbz));
        tmin = fminf(fmaxf(tmin, 0.2f), 3.0f);
        float tmax = fminf(fminf(fmaxf(rax,rbx), fmaxf(ray_,rby)), fmaxf(raz,rbz));
        tmax = fminf(fmaxf(tmax, 0.2f), 3.0f);
        bool maskray = (tmax <= tmin);
        float invn = 1.f / sqrtf(dx*dx + dy*dy + dz*dz);

        int lmin = 0x7fffffff, lmax = -1;
        for (int s=tid; s<NS; s+=256){
            float t  = tmin + (0.0078125f * (float)s) * invn;
            float px = fmaf(dx, t, ox), py = fmaf(dy, t, oy), pz = fmaf(dz, t, oz);
            bool in = (!maskray) &&
                      !(px < -1.f || px > 1.f || py < -1.f || py > 1.f || pz < -1.f || pz > 1.f);
            float a = 0.f;
            if (in){
                int off[8]; float wc[8];
                tri_setup(px, py, pz, off, wc);
                float l0 = 0.f;
                #pragma unroll
                for (int k=0; k<8; k++) l0 = fmaf(wc[k], __ldg(dens + off[k]), l0);
                float xs = l0 + ACT_SHIFT;
                float sp = fmaxf(xs, 0.f) + log1pf(expf(-fabsf(xs)));
                a = 1.f - expf(-sp*0.5f);
                lmin = min(lmin, s); lmax = max(lmax, s);
            }
            aw[s] = a;
        }
        if (lmax >= 0){ atomicMin(&s_min, lmin); atomicMax(&s_max, lmax); }
        __syncthreads();

        // parallel transmittance scan: 4 contiguous samples / thread
        int base4 = tid*4;
        float lp = 1.f;
        #pragma unroll
        for (int j=0; j<4; j++){
            int s = base4 + j;
            if (s < NS) lp *= fmaxf(1.f - aw[s], 1e-10f);
        }
        float v = lp;
        #pragma unroll
        for (int o=1; o<32; o<<=1){
            float n = __shfl_up_sync(0xffffffffu, v, o);
            if (lane >= o) v *= n;
        }
        if (lane == 31) s_wprod[wid] = v;
        __syncthreads();
        float warp_excl = 1.f;
        #pragma unroll
        for (int wj=0; wj<8; wj++)
            if (wj < wid) warp_excl *= s_wprod[wj];
        float vexcl = __shfl_up_sync(0xffffffffu, v, 1);
        if (lane == 0) vexcl = 1.f;
        float T = warp_excl * vexcl;

        int smn = s_min, smx = s_max;
        #pragma unroll
        for (int j=0; j<4; j++){
            int s = base4 + j;
            if (s < NS){
                float a = aw[s];
                if (s >= smn && s <= smx)
                    g_w[rid*NS + s] = a * T;
                T *= fmaxf(1.f - a, 1e-10f);
            }
        }

        if (tid == 0){
            float Tall = 1.f;
            #pragma unroll
            for (int wj=0; wj<8; wj++) Tall *= s_wprod[wj];
            g_T[rid]    = Tall;
            g_tmin[rid] = tmin;
            g_invn[rid] = invn;
            int cnt = (smx >= smn) ? (smx - smn + 1) : 0;
            g_sstart[rid] = (cnt > 0) ? smn : 0;
            g_scnt[rid]   = cnt;
        }
    }
}

// ---------------------------------------------------------------------------
// Kernel 2: exclusive scan + work reset + out init (out = T * BG, BG=1).
// ---------------------------------------------------------------------------
__global__ void __launch_bounds__(1024) scan_kernel(float* __restrict__ out)
{
    __shared__ int wsum[32];
    int t = threadIdx.x;
    int lane = t & 31, wid = t >> 5;
    int v = g_scnt[t];
    #pragma unroll
    for (int o=1; o<32; o<<=1){
        int n = __shfl_up_sync(0xffffffffu, v, o);
        if (lane >= o) v += n;
    }
    if (lane == 31) wsum[wid] = v;
    __syncthreads();
    if (wid == 0){
        int w = wsum[lane];
        #pragma unroll
        for (int o=1; o<32; o<<=1){
            int n = __shfl_up_sync(0xffffffffu, w, o);
            if (lane >= o) w += n;
        }
        wsum[lane] = w;
    }
    __syncthreads();
    if (wid > 0) v += wsum[wid-1];
    g_base[t+1] = v;
    if (t == 0){ g_base[0] = 0; g_work = 0; }
    if (t == 1023) g_total = v;

    float Tf = g_T[t];
    out[t*3+0] = Tf;
    out[t*3+1] = Tf;
    out[t*3+2] = Tf;
}

// ---------------------------------------------------------------------------
// Kernel 3: pair-split MLP. Per-warp SEGMENTED reduction over ray boundaries,
// then one atomicAdd per (ray,channel) segment (few per chunk, low contention).
// ---------------------------------------------------------------------------
#define OFF_W0    0
#define OFF_W1    3464
#define OFF_W2    7568
#define OFF_W3    11672
#define OFF_B0    11864
#define OFF_B1    11928
#define OFF_B2    11992
#define OFF_B3    12056
#define OFF_BASE  12060
#define OFF_STAGE 13088
#define MLP_NTH   384
#define SH_FLOATS (OFF_STAGE + (MLP_NTH/2)*130)
#define SMEM_MLP  (SH_FLOATS*4)
#define MLP_BLOCKS 148

__device__ __forceinline__ void gemv_pair(u64* hA, u64* hB,
                                          const float* wbase,
                                          const float* fp, int R)
{
    for (int i=0; i<R; i++){
        float2 vp = *(const float2*)(fp + i*2);
        u64 vvA = f2pack(vp.x, vp.x);
        u64 vvB = f2pack(vp.y, vp.y);
        const ulonglong2* wr = (const ulonglong2*)(wbase + i*32);
        #pragma unroll
        for (int k=0; k<8; k++){
            ulonglong2 w2 = wr[k];
            hA[2*k]   = ffma2(vvA, w2.x, hA[2*k]);
            hA[2*k+1] = ffma2(vvA, w2.y, hA[2*k+1]);
            hB[2*k]   = ffma2(vvB, w2.x, hB[2*k]);
            hB[2*k+1] = ffma2(vvB, w2.y, hB[2*k+1]);
        }
    }
}

__device__ __forceinline__ void bias_init(u64* hA, u64* hB,
                                          const float* bias, int hf)
{
    const u64* bp = (const u64*)bias;
    #pragma unroll
    for (int k=0; k<16; k++){ u64 bb = bp[hf*16 + k]; hA[k]=bb; hB[k]=bb; }
}

__device__ __forceinline__ void relu_stage(const u64* hA, const u64* hB,
                                           float* fp, int hf)
{
    #pragma unroll
    for (int k=0; k<16; k++){
        float a0,a1,b0,b1;
        f2unpack(hA[k], a0, a1);
        f2unpack(hB[k], b0, b1);
        a0 = fmaxf(a0,0.f); a1 = fmaxf(a1,0.f);
        b0 = fmaxf(b0,0.f); b1 = fmaxf(b1,0.f);
        int n = hf*32 + 2*k;
        *(float2*)(fp + n*2)     = make_float2(a0, b0);
        *(float2*)(fp + n*2 + 2) = make_float2(a1, b1);
    }
}

__global__ void __launch_bounds__(MLP_NTH, 1) mlp_kernel(
    const float* __restrict__ ro,  const float* __restrict__ rdv,
    const float* __restrict__ vdv, const float* __restrict__ grid,
    const float* __restrict__ w0,  const float* __restrict__ b0,
    const float* __restrict__ w1,  const float* __restrict__ b1,
    const float* __restrict__ w2,  const float* __restrict__ b2,
    const float* __restrict__ w3,  const float* __restrict__ b3,
    float* __restrict__ out)
{
    extern __shared__ float sh[];
    int tid  = threadIdx.x;
    int lane = tid & 31;
    int hf   = tid & 1;
    int pg   = tid >> 1;
    int* sbase = (int*)(sh + OFF_BASE);

    for (int i=tid; i<54*64; i+=MLP_NTH){
        int r = i>>6, j = i&63;
        int dst = (j<32) ? (r*32+j) : (54*32+4 + r*32 + (j-32));
        sh[OFF_W0+dst] = w0[i];
    }
    for (int i=tid; i<64*64; i+=MLP_NTH){
        int r = i>>6, j = i&63;
        int dst = (j<32) ? (r*32+j) : (64*32+4 + r*32 + (j-32));
        sh[OFF_W1+dst] = w1[i];
        sh[OFF_W2+dst] = w2[i];
    }
    for (int i=tid; i<192; i+=MLP_NTH) sh[OFF_W3+i] = w3[i];
    for (int i=tid; i<64;  i+=MLP_NTH){
        sh[OFF_B0+i]=b0[i]; sh[OFF_B1+i]=b1[i]; sh[OFF_B2+i]=b2[i];
    }
    if (tid < 3) sh[OFF_B3+tid] = b3[tid];
    for (int i=tid; i<NRAYS+1; i+=MLP_NTH) sbase[i] = g_base[i];
    __syncthreads();

    int total   = g_total;
    int nchunks = (total + 31) >> 5;
    float* fp = sh + OFF_STAGE + pg*130;
    const float* wl0 = sh + OFF_W0 + hf*(54*32+4);
    const float* wl1 = sh + OFF_W1 + hf*(64*32+4);
    const float* wl2 = sh + OFF_W2 + hf*(64*32+4);

    while (true){
        int chunk = 0;
        if (lane == 0) chunk = atomicAdd(&g_work, 1);
        chunk = __shfl_sync(0xffffffffu, chunk, 0);
        if (chunk >= nchunks) break;
        int e = chunk*32 + lane;
        bool valid = (e < total);
        int ec = valid ? e : (total - 1);

        int lo = 0, hi = NRAYS;
        while (hi - lo > 1){
            int mid = (lo + hi) >> 1;
            if (sbase[mid] <= ec) lo = mid; else hi = mid;
        }
        int ray = lo;
        int s = g_sstart[ray] + (ec - sbase[ray]);

        float ox = __ldg(ro+ray*3+0), oy = __ldg(ro+ray*3+1), oz = __ldg(ro+ray*3+2);
        float dx = __ldg(rdv+ray*3+0), dy = __ldg(rdv+ray*3+1), dz = __ldg(rdv+ray*3+2);
        float vx = __ldg(vdv+ray*3+0), vy = __ldg(vdv+ray*3+1), vz = __ldg(vdv+ray*3+2);
        float tmin = __ldg(&g_tmin[ray]);
        float invn = __ldg(&g_invn[ray]);
        float wgt  = __ldg(&g_w[ray*NS + s]);

        float t  = tmin + (0.0078125f * (float)s) * invn;
        float px = fmaf(dx, t, ox), py = fmaf(dy, t, oy), pz = fmaf(dz, t, oz);

        int off[8]; float wc[8];
        tri_setup(px, py, pz, off, wc);

        float nvx[8], nvy[8], nvz[8];
        #pragma unroll
        for (int k=0; k<8; k++){
            nvx[k] = __ldg(g_norm + off[k]);
            nvy[k] = __ldg(g_norm + NVOX + off[k]);
            nvz[k] = __ldg(g_norm + 2*NVOX + off[k]);
        }

        for (int ch=1; ch<=15; ++ch){
            const float* gp = grid + ch*NVOX;
            float v = 0.f;
            #pragma unroll
            for (int k=0; k<8; k++) v = fmaf(wc[k], __ldg(gp + off[k]), v);
            fp[(ch-1)*2 + hf] = v;
        }

        float nsx = 0.f, nsy = 0.f, nsz = 0.f;
        #pragma unroll
        for (int k=0; k<8; k++){
            nsx = fmaf(wc[k], nvx[k], nsx);
            nsy = fmaf(wc[k], nvy[k], nsy);
            nsz = fmaf(wc[k], nvz[k], nsz);
        }
        float nl = sqrtf(nsx*nsx + nsy*nsy + nsz*nsz);
        float ninv = -1.f / fmaxf(nl, 1e-12f);
        nsx *= ninv; nsy *= ninv; nsz *= ninv;
        float dt  = -(vx*nsx + vy*nsy + vz*nsz);
        float rx = fmaf(2.f*dt, nsx, vx);
        float ry = fmaf(2.f*dt, nsy, vy);
        float rz = fmaf(2.f*dt, nsz, vz);
        fp[15*2 + hf] = rx;
        fp[16*2 + hf] = ry;
        fp[17*2 + hf] = rz;

        for (int f=0; f<6; ++f){
            float fr = (float)(1 << f);
            #pragma unroll
            for (int k3=0; k3<3; k3++){
                float ang = (k3==0 ? rx : (k3==1 ? ry : rz)) * fr;
                float kk = rintf(ang * 0.15915494309189535f);
                float r2 = fmaf(kk, -6.283185307179586f, ang);
                float sn, cs;
                sincosf(r2, &sn, &cs);
                fp[(18 + f*3 + k3)*2 + hf] = sn;
                fp[(36 + f*3 + k3)*2 + hf] = cs;
            }
        }
        __syncwarp();

        u64 hA[16], hB[16];
        bias_init(hA, hB, sh + OFF_B0, hf);
        gemv_pair(hA, hB, wl0, fp, 54);
        __syncwarp();
        relu_stage(hA, hB, fp, hf);
        __syncwarp();

        bias_init(hA, hB, sh + OFF_B1, hf);
        gemv_pair(hA, hB, wl1, fp, 64);
        __syncwarp();
        relu_stage(hA, hB, fp, hf);
        __syncwarp();

        bias_init(hA, hB, sh + OFF_B2, hf);
        gemv_pair(hA, hB, wl2, fp, 64);

        float pA0=0.f,pA1=0.f,pA2=0.f,pB0=0.f,pB1=0.f,pB2=0.f;
        #pragma unroll
        for (int k=0; k<16; k++){
            float a0,a1,b0v,b1v;
            f2unpack(hA[k], a0, a1);
            f2unpack(hB[k], b0v, b1v);
            a0 = fmaxf(a0,0.f); a1 = fmaxf(a1,0.f);
            b0v = fmaxf(b0v,0.f); b1v = fmaxf(b1v,0.f);
            int n0 = hf*32 + 2*k;
            float q00 = sh[OFF_W3 + n0*3 + 0];
            float q01 = sh[OFF_W3 + n0*3 + 1];
            float q02 = sh[OFF_W3 + n0*3 + 2];
            float q10 = sh[OFF_W3 + n0*3 + 3];
            float q11 = sh[OFF_W3 + n0*3 + 4];
            float q12 = sh[OFF_W3 + n0*3 + 5];
            pA0 = fmaf(a0,q00, fmaf(a1,q10, pA0));
            pA1 = fmaf(a0,q01, fmaf(a1,q11, pA1));
            pA2 = fmaf(a0,q02, fmaf(a1,q12, pA2));
            pB0 = fmaf(b0v,q00, fmaf(b1v,q10, pB0));
            pB1 = fmaf(b0v,q01, fmaf(b1v,q11, pB1));
            pB2 = fmaf(b0v,q02, fmaf(b1v,q12, pB2));
        }
        pA0 += __shfl_xor_sync(0xffffffffu, pA0, 1);
        pA1 += __shfl_xor_sync(0xffffffffu, pA1, 1);
        pA2 += __shfl_xor_sync(0xffffffffu, pA2, 1);
        pB0 += __shfl_xor_sync(0xffffffffu, pB0, 1);
        pB1 += __shfl_xor_sync(0xffffffffu, pB1, 1);
        pB2 += __shfl_xor_sync(0xffffffffu, pB2, 1);

        float c0s = (hf ? pB0 : pA0) + sh[OFF_B3+0];
        float c1s = (hf ? pB1 : pA1) + sh[OFF_B3+1];
        float c2s = (hf ? pB2 : pA2) + sh[OFF_B3+2];
        float o0 = valid ? wgt / (1.f + expf(-c0s)) : 0.f;
        float o1 = valid ? wgt / (1.f + expf(-c1s)) : 0.f;
        float o2 = valid ? wgt / (1.f + expf(-c2s)) : 0.f;

        // ---- warp-segmented sum keyed on ray (non-decreasing across lanes) --
        #pragma unroll
        for (int o=1; o<32; o<<=1){
            float n0 = __shfl_up_sync(0xffffffffu, o0, o);
            float n1 = __shfl_up_sync(0xffffffffu, o1, o);
            float n2 = __shfl_up_sync(0xffffffffu, o2, o);
            int   rr = __shfl_up_sync(0xffffffffu, ray, o);
            if (lane >= o && rr == ray){ o0 += n0; o1 += n1; o2 += n2; }
        }
        int rnext = __shfl_down_sync(0xffffffffu, ray, 1);
        bool seglast = (lane == 31) || (rnext != ray);
        if (seglast){
            atomicAdd(&out[ray*3+0], o0);
            atomicAdd(&out[ray*3+1], o1);
            atomicAdd(&out[ray*3+2], o2);
        }
    }
}

extern "C" void kernel_launch(void* const* d_in, const int* in_sizes, int n_in,
                              void* d_out, int out_size)
{
    (void)in_sizes; (void)n_in; (void)out_size;
    const float* ro    = (const float*)d_in[0];
    const float* rd    = (const float*)d_in[1];
    const float* vd    = (const float*)d_in[2];
    const float* grid  = (const float*)d_in[3];
    const float* sobel = (const float*)d_in[4];
    const float* w0 = (const float*)d_in[5];
    const float* b0 = (const float*)d_in[6];
    const float* w1 = (const float*)d_in[7];
    const float* b1 = (const float*)d_in[8];
    const float* w2 = (const float*)d_in[9];
    const float* b2 = (const float*)d_in[10];
    const float* w3 = (const float*)d_in[11];
    const float* b3 = (const float*)d_in[12];
    float* out = (float*)d_out;

    fused_kernel<<<CONV_BLOCKS + NRAYS, 256>>>(grid, sobel, ro, rd);
    scan_kernel<<<1, 1024>>>(out);

    static int smem_set = 0;
    if (!smem_set){
        cudaFuncSetAttribute(mlp_kernel,
                             cudaFuncAttributeMaxDynamicSharedMemorySize, SMEM_MLP);
        smem_set = 1;
    }
    mlp_kernel<<<MLP_BLOCKS, MLP_NTH, SMEM_MLP>>>(ro, rd, vd, grid,
                                                  w0, b0, w1, b1, w2, b2, w3, b3, out);
}

// round 13
// speedup vs baseline: 1.0718x; 1.0216x over previous
#include <cuda_runtime.h>
#include <math.h>

#define RESX   128
#define NVOX   (RESX*RESX*RESX)
#define NRAYS  1024
#define NS     891

#define ACT_SHIFT (-4.5951198501345898f)

// ---------------- global scratch ----------------
__device__ float g_norm[3*NVOX];
__device__ float g_w[NRAYS*NS];
__device__ float g_T[NRAYS];
__device__ float g_tmin[NRAYS];
__device__ float g_invn[NRAYS];
__device__ int   g_sstart[NRAYS];
__device__ int   g_scnt[NRAYS];
__device__ int   g_base[NRAYS+1];
__device__ int   g_total;
__device__ int   g_work;
__device__ float g_c0[NRAYS*NS];
__device__ float g_c1[NRAYS*NS];
__device__ float g_c2[NRAYS*NS];

// ---------------------------------------------------------------------------
// packed fp32x2 helpers
// ---------------------------------------------------------------------------
typedef unsigned long long u64;
__device__ __forceinline__ u64 f2pack(float lo, float hi){
    u64 r; asm("mov.b64 %0,{%1,%2};" : "=l"(r) : "f"(lo), "f"(hi)); return r;
}
__device__ __forceinline__ void f2unpack(u64 v, float& lo, float& hi){
    asm("mov.b64 {%0,%1},%2;" : "=f"(lo), "=f"(hi) : "l"(v));
}
__device__ __forceinline__ u64 ffma2(u64 a, u64 b, u64 c){
    u64 d; asm("fma.rn.f32x2 %0,%1,%2,%3;" : "=l"(d) : "l"(a), "l"(b), "l"(c)); return d;
}

__device__ __forceinline__ void tri_setup(float px, float py, float pz,
                                          int* off, float* w)
{
    float ga = (px + 1.f)*0.5f*127.f;
    float gb = (py + 1.f)*0.5f*127.f;
    float gc = (pz + 1.f)*0.5f*127.f;
    float fa0 = floorf(ga), fb0 = floorf(gb), fc0 = floorf(gc);
    float fa = ga - fa0, fb = gb - fb0, fc = gc - fc0;
    int a0 = min(max((int)fa0, 0), 127);
    int b0 = min(max((int)fb0, 0), 127);
    int c0 = min(max((int)fc0, 0), 127);
    int a1 = min(a0+1, 127), b1 = min(b0+1, 127), c1 = min(c0+1, 127);
    int A0 = a0*16384, A1 = a1*16384, B0 = b0*128, B1 = b1*128;
    off[0]=A0+B0+c0; off[1]=A0+B0+c1; off[2]=A0+B1+c0; off[3]=A0+B1+c1;
    off[4]=A1+B0+c0; off[5]=A1+B0+c1; off[6]=A1+B1+c0; off[7]=A1+B1+c1;
    float wa0 = 1.f-fa, wb0 = 1.f-fb, wc0 = 1.f-fc;
    w[0]=wa0*wb0*wc0; w[1]=wa0*wb0*fc; w[2]=wa0*fb*wc0; w[3]=wa0*fb*fc;
    w[4]=fa*wb0*wc0;  w[5]=fa*wb0*fc;  w[6]=fa*fb*wc0;  w[7]=fa*fb*fc;
}

// ---------------------------------------------------------------------------
// Kernel 1: FUSED conv (blocks 0..2047, f32x2 with PRE-PACKED kernel taps)
// + prep (2048..3071, parallel transmittance scan).
// ---------------------------------------------------------------------------
#define CONV_BLOCKS 2048
__global__ void __launch_bounds__(256) fused_kernel(
    const float* __restrict__ dens, const float* __restrict__ kern,
    const float* __restrict__ ro,   const float* __restrict__ rdv)
{
    __shared__ float smem_u[8*12*36];     // conv: tile; prep: aw (891)
    __shared__ u64   skp[375];            // conv only: pre-packed (k,k)
    __shared__ float s_wprod[8];
    __shared__ int s_min, s_max;

    if (blockIdx.x < CONV_BLOCKS){
        // ----------------- conv path -----------------
        float* tile = smem_u;
        int bid = blockIdx.x;
        int tc = threadIdx.x & 31;
        int tb = (threadIdx.x >> 5);
        int tid = threadIdx.x;
        int c0 = (bid & 3)*32;
        int b0 = ((bid >> 2) & 15)*8;
        int a0 = (bid >> 6)*4;

        for (int i=tid; i<375; i+=256){
            float k = kern[i];
            skp[i] = f2pack(k, k);
        }
        for (int i=tid; i<8*12*36; i+=256){
            int ic = i % 36; int r = i / 36; int ib = r % 12; int ia = r / 12;
            int ga = a0 - 2 + ia, gb = b0 - 2 + ib, gc = c0 - 2 + ic;
            float v = 0.f;
            if ((unsigned)ga < 128u && (unsigned)gb < 128u && (unsigned)gc < 128u)
                v = dens[(ga*128 + gb)*128 + gc];
            tile[i] = v;
        }
        __syncthreads();

        u64 s0p[2]={0,0}, s1p[2]={0,0}, s2p[2]={0,0};
        for (int db=0; db<5; db++){
            for (int dc=0; dc<5; dc++){
                float tv[8];
                #pragma unroll
                for (int ia=0; ia<8; ia++)
                    tv[ia] = tile[(ia*12 + tb + db)*36 + tc + dc];
                u64 p[7];
                #pragma unroll
                for (int i=0; i<7; i++) p[i] = f2pack(tv[i], tv[i+1]);
                #pragma unroll
                for (int da=0; da<5; da++){
                    u64 kp0 = skp[0*125 + da*25 + db*5 + dc];
                    u64 kp1 = skp[1*125 + da*25 + db*5 + dc];
                    u64 kp2 = skp[2*125 + da*25 + db*5 + dc];
                    s0p[0] = ffma2(kp0, p[da],   s0p[0]);
                    s0p[1] = ffma2(kp0, p[da+2], s0p[1]);
                    s1p[0] = ffma2(kp1, p[da],   s1p[0]);
                    s1p[1] = ffma2(kp1, p[da+2], s1p[1]);
                    s2p[0] = ffma2(kp2, p[da],   s2p[0]);
                    s2p[1] = ffma2(kp2, p[da+2], s2p[1]);
                }
            }
        }
        float s0[4], s1[4], s2[4];
        f2unpack(s0p[0], s0[0], s0[1]); f2unpack(s0p[1], s0[2], s0[3]);
        f2unpack(s1p[0], s1[0], s1[1]); f2unpack(s1p[1], s1[2], s1[3]);
        f2unpack(s2p[0], s2[0], s2[1]); f2unpack(s2p[1], s2[2], s2[3]);
        #pragma unroll
        for (int v=0; v<4; v++){
            int idx = ((a0+v)*128 + (b0+tb))*128 + (c0+tc);
            float n0 = s0[v], n1 = s1[v], n2 = s2[v];
            float len = sqrtf(n0*n0 + n1*n1 + n2*n2);
            float inv = -1.f / fmaxf(len, 1e-12f);
            g_norm[idx]          = n0*inv;
            g_norm[NVOX + idx]   = n1*inv;
            g_norm[2*NVOX + idx] = n2*inv;
        }
    } else {
        // ----------------- prep path -----------------
        float* aw = smem_u;
        int tid = threadIdx.x;
        int lane = tid & 31, wid = tid >> 5;
        int rid = blockIdx.x - CONV_BLOCKS;
        if (tid == 0){ s_min = 0x7fffffff; s_max = -1; }
        __syncthreads();

        float ox = ro[rid*3+0], oy = ro[rid*3+1], oz = ro[rid*3+2];
        float dx = rdv[rid*3+0], dy = rdv[rid*3+1], dz = rdv[rid*3+2];

        float vecx = (dx == 0.f) ? 1e-6f : dx;
        float vecy = (dy == 0.f) ? 1e-6f : dy;
        float vecz = (dz == 0.f) ? 1e-6f : dz;
        float rax = ( 1.f - ox)/vecx, rbx = (-1.f - ox)/vecx;
        float ray_ = ( 1.f - oy)/vecy, rby = (-1.f - oy)/vecy;
        float raz = ( 1.f - oz)/vecz, rbz = (-1.f - oz)/vecz;
        float tmin = fmaxf(fmaxf(fminf(rax,rbx), fminf(ray_,rby)), fminf(raz,rbz));
        tmin = fminf(fmaxf(tmin, 0.2f), 3.0f);
        float tmax = fminf(fminf(fmaxf(rax,rbx), fmaxf(ray_,rby)), fmaxf(raz,rbz));
        tmax = fminf(fmaxf(tmax, 0.2f), 3.0f);
        bool maskray = (tmax <= tmin);
        float invn = 1.f / sqrtf(dx*dx + dy*dy + dz*dz);

        int lmin = 0x7fffffff, lmax = -1;
        for (int s=tid; s<NS; s+=256){
            float t  = tmin + (0.0078125f * (float)s) * invn;
            float px = fmaf(dx, t, ox), py = fmaf(dy, t, oy), pz = fmaf(dz, t, oz);
            bool in = (!maskray) &&
                      !(px < -1.f || px > 1.f || py < -1.f || py > 1.f || pz < -1.f || pz > 1.f);
            float a = 0.f;
            if (in){
                int off[8]; float wc[8];
                tri_setup(px, py, pz, off, wc);
                float l0 = 0.f;
                #pragma unroll
                for (int k=0; k<8; k++) l0 = fmaf(wc[k], __ldg(dens + off[k]), l0);
                float xs = l0 + ACT_SHIFT;
                float sp = fmaxf(xs, 0.f) + log1pf(expf(-fabsf(xs)));
                a = 1.f - expf(-sp*0.5f);
                lmin = min(lmin, s); lmax = max(lmax, s);
            }
            aw[s] = a;
        }
        if (lmax >= 0){ atomicMin(&s_min, lmin); atomicMax(&s_max, lmax); }
        __syncthreads();

        // parallel transmittance scan: 4 contiguous samples / thread
        int base4 = tid*4;
        float lp = 1.f;
        #pragma unroll
        for (int j=0; j<4; j++){
            int s = base4 + j;
            if (s < NS) lp *= fmaxf(1.f - aw[s], 1e-10f);
        }
        float v = lp;
        #pragma unroll
        for (int o=1; o<32; o<<=1){
            float n = __shfl_up_sync(0xffffffffu, v, o);
            if (lane >= o) v *= n;
        }
        if (lane == 31) s_wprod[wid] = v;
        __syncthreads();
        float warp_excl = 1.f;
        #pragma unroll
        for (int wj=0; wj<8; wj++)
            if (wj < wid) warp_excl *= s_wprod[wj];
        float vexcl = __shfl_up_sync(0xffffffffu, v, 1);
        if (lane == 0) vexcl = 1.f;
        float T = warp_excl * vexcl;

        int smn = s_min, smx = s_max;
        #pragma unroll
        for (int j=0; j<4; j++){
            int s = base4 + j;
            if (s < NS){
                float a = aw[s];
                if (s >= smn && s <= smx)
                    g_w[rid*NS + s] = a * T;
                T *= fmaxf(1.f - a, 1e-10f);
            }
        }

        if (tid == 0){
            float Tall = 1.f;
            #pragma unroll
            for (int wj=0; wj<8; wj++) Tall *= s_wprod[wj];
            g_T[rid]    = Tall;
            g_tmin[rid] = tmin;
            g_invn[rid] = invn;
            int cnt = (smx >= smn) ? (smx - smn + 1) : 0;
            g_sstart[rid] = (cnt > 0) ? smn : 0;
            g_scnt[rid]   = cnt;
        }
    }
}

// ---------------------------------------------------------------------------
// Kernel 2: shuffle-based exclusive scan + work reset.
// ---------------------------------------------------------------------------
__global__ void __launch_bounds__(1024) scan_kernel()
{
    __shared__ int wsum[32];
    int t = threadIdx.x;
    int lane = t & 31, wid = t >> 5;
    int v = g_scnt[t];
    #pragma unroll
    for (int o=1; o<32; o<<=1){
        int n = __shfl_up_sync(0xffffffffu, v, o);
        if (lane >= o) v += n;
    }
    if (lane == 31) wsum[wid] = v;
    __syncthreads();
    if (wid == 0){
        int w = wsum[lane];
        #pragma unroll
        for (int o=1; o<32; o<<=1){
            int n = __shfl_up_sync(0xffffffffu, w, o);
            if (lane >= o) w += n;
        }
        wsum[lane] = w;
    }
    __syncthreads();
    if (wid > 0) v += wsum[wid-1];
    g_base[t+1] = v;
    if (t == 0){ g_base[0] = 0; g_work = 0; }
    if (t == 1023) g_total = v;
}

// ---------------------------------------------------------------------------
// Kernel 3: pair-split MLP, per-entry results to g_c scratch (R7-proven
// epilogue), sincos via doubling recurrence (freqs are powers of 2).
// ---------------------------------------------------------------------------
#define OFF_W0    0
#define OFF_W1    3464
#define OFF_W2    7568
#define OFF_W3    11672
#define OFF_B0    11864
#define OFF_B1    11928
#define OFF_B2    11992
#define OFF_B3    12056
#define OFF_BASE  12060
#define OFF_STAGE 13088
#define MLP_NTH   384
#define SH_FLOATS (OFF_STAGE + (MLP_NTH/2)*130)
#define SMEM_MLP  (SH_FLOATS*4)
#define MLP_BLOCKS 148

__device__ __forceinline__ void gemv_pair(u64* hA, u64* hB,
                                          const float* wbase,
                                          const float* fp, int R)
{
    for (int i=0; i<R; i++){
        float2 vp = *(const float2*)(fp + i*2);
        u64 vvA = f2pack(vp.x, vp.x);
        u64 vvB = f2pack(vp.y, vp.y);
        const ulonglong2* wr = (const ulonglong2*)(wbase + i*32);
        #pragma unroll
        for (int k=0; k<8; k++){
            ulonglong2 w2 = wr[k];
            hA[2*k]   = ffma2(vvA, w2.x, hA[2*k]);
            hA[2*k+1] = ffma2(vvA, w2.y, hA[2*k+1]);
            hB[2*k]   = ffma2(vvB, w2.x, hB[2*k]);
            hB[2*k+1] = ffma2(vvB, w2.y, hB[2*k+1]);
        }
    }
}

__device__ __forceinline__ void bias_init(u64* hA, u64* hB,
                                          const float* bias, int hf)
{
    const u64* bp = (const u64*)bias;
    #pragma unroll
    for (int k=0; k<16; k++){ u64 bb = bp[hf*16 + k]; hA[k]=bb; hB[k]=bb; }
}

__device__ __forceinline__ void relu_stage(const u64* hA, const u64* hB,
                                           float* fp, int hf)
{
    #pragma unroll
    for (int k=0; k<16; k++){
        float a0,a1,b0,b1;
        f2unpack(hA[k], a0, a1);
        f2unpack(hB[k], b0, b1);
        a0 = fmaxf(a0,0.f); a1 = fmaxf(a1,0.f);
        b0 = fmaxf(b0,0.f); b1 = fmaxf(b1,0.f);
        int n = hf*32 + 2*k;
        *(float2*)(fp + n*2)     = make_float2(a0, b0);
        *(float2*)(fp + n*2 + 2) = make_float2(a1, b1);
    }
}

__global__ void __launch_bounds__(MLP_NTH, 1) mlp_kernel(
    const float* __restrict__ ro,  const float* __restrict__ rdv,
    const float* __restrict__ vdv, const float* __restrict__ grid,
    const float* __restrict__ w0,  const float* __restrict__ b0,
    const float* __restrict__ w1,  const float* __restrict__ b1,
    const float* __restrict__ w2,  const float* __restrict__ b2,
    const float* __restrict__ w3,  const float* __restrict__ b3)
{
    extern __shared__ float sh[];
    int tid  = threadIdx.x;
    int lane = tid & 31;
    int hf   = tid & 1;
    int pg   = tid >> 1;
    int* sbase = (int*)(sh + OFF_BASE);

    for (int i=tid; i<54*64; i+=MLP_NTH){
        int r = i>>6, j = i&63;
        int dst = (j<32) ? (r*32+j) : (54*32+4 + r*32 + (j-32));
        sh[OFF_W0+dst] = w0[i];
    }
    for (int i=tid; i<64*64; i+=MLP_NTH){
        int r = i>>6, j = i&63;
        int dst = (j<32) ? (r*32+j) : (64*32+4 + r*32 + (j-32));
        sh[OFF_W1+dst] = w1[i];
        sh[OFF_W2+dst] = w2[i];
    }
    for (int i=tid; i<192; i+=MLP_NTH) sh[OFF_W3+i] = w3[i];
    for (int i=tid; i<64;  i+=MLP_NTH){
        sh[OFF_B0+i]=b0[i]; sh[OFF_B1+i]=b1[i]; sh[OFF_B2+i]=b2[i];
    }
    if (tid < 3) sh[OFF_B3+tid] = b3[tid];
    for (int i=tid; i<NRAYS+1; i+=MLP_NTH) sbase[i] = g_base[i];
    __syncthreads();

    int total   = g_total;
    int nchunks = (total + 31) >> 5;
    float* fp = sh + OFF_STAGE + pg*130;
    const float* wl0 = sh + OFF_W0 + hf*(54*32+4);
    const float* wl1 = sh + OFF_W1 + hf*(64*32+4);
    const float* wl2 = sh + OFF_W2 + hf*(64*32+4);

    while (true){
        int chunk = 0;
        if (lane == 0) chunk = atomicAdd(&g_work, 1);
        chunk = __shfl_sync(0xffffffffu, chunk, 0);
        if (chunk >= nchunks) break;
        int e = chunk*32 + lane;
        bool valid = (e < total);
        int ec = valid ? e : (total - 1);

        int lo = 0, hi = NRAYS;
        while (hi - lo > 1){
            int mid = (lo + hi) >> 1;
            if (sbase[mid] <= ec) lo = mid; else hi = mid;
        }
        int ray = lo;
        int s = g_sstart[ray] + (ec - sbase[ray]);

        float ox = __ldg(ro+ray*3+0), oy = __ldg(ro+ray*3+1), oz = __ldg(ro+ray*3+2);
        float dx = __ldg(rdv+ray*3+0), dy = __ldg(rdv+ray*3+1), dz = __ldg(rdv+ray*3+2);
        float vx = __ldg(vdv+ray*3+0), vy = __ldg(vdv+ray*3+1), vz = __ldg(vdv+ray*3+2);
        float tmin = __ldg(&g_tmin[ray]);
        float invn = __ldg(&g_invn[ray]);
        float wgt  = __ldg(&g_w[ray*NS + s]);

        float t  = tmin + (0.0078125f * (float)s) * invn;
        float px = fmaf(dx, t, ox), py = fmaf(dy, t, oy), pz = fmaf(dz, t, oz);

        int off[8]; float wc[8];
        tri_setup(px, py, pz, off, wc);

        float nvx[8], nvy[8], nvz[8];
        #pragma unroll
        for (int k=0; k<8; k++){
            nvx[k] = __ldg(g_norm + off[k]);
            nvy[k] = __ldg(g_norm + NVOX + off[k]);
            nvz[k] = __ldg(g_norm + 2*NVOX + off[k]);
        }

        for (int ch=1; ch<=15; ++ch){
            const float* gp = grid + ch*NVOX;
            float v = 0.f;
            #pragma unroll
            for (int k=0; k<8; k++) v = fmaf(wc[k], __ldg(gp + off[k]), v);
            fp[(ch-1)*2 + hf] = v;
        }

        float nsx = 0.f, nsy = 0.f, nsz = 0.f;
        #pragma unroll
        for (int k=0; k<8; k++){
            nsx = fmaf(wc[k], nvx[k], nsx);
            nsy = fmaf(wc[k], nvy[k], nsy);
            nsz = fmaf(wc[k], nvz[k], nsz);
        }
        float nl = sqrtf(nsx*nsx + nsy*nsy + nsz*nsz);
        float ninv = -1.f / fmaxf(nl, 1e-12f);
        nsx *= ninv; nsy *= ninv; nsz *= ninv;
        float dt  = -(vx*nsx + vy*nsy + vz*nsz);
        float rx = fmaf(2.f*dt, nsx, vx);
        float ry = fmaf(2.f*dt, nsy, vy);
        float rz = fmaf(2.f*dt, nsz, vz);
        fp[15*2 + hf] = rx;
        fp[16*2 + hf] = ry;
        fp[17*2 + hf] = rz;

        // sin/cos of r*2^f via doubling recurrence (freqs are powers of 2):
        // one sincosf per axis, then s'=2sc, c'=1-2s^2 per octave.
        {
            float sv[3], cv3[3];
            sincosf(rx, &sv[0], &cv3[0]);
            sincosf(ry, &sv[1], &cv3[1]);
            sincosf(rz, &sv[2], &cv3[2]);
            #pragma unroll
            for (int f=0; f<6; ++f){
                #pragma unroll
                for (int k3=0; k3<3; k3++){
                    fp[(18 + f*3 + k3)*2 + hf] = sv[k3];
                    fp[(36 + f*3 + k3)*2 + hf] = cv3[k3];
                }
                if (f < 5){
                    #pragma unroll
                    for (int k3=0; k3<3; k3++){
                        float sn = sv[k3], cn = cv3[k3];
                        sv[k3]  = 2.f*sn*cn;
                        cv3[k3] = fmaf(-2.f*sn, sn, 1.f);
                    }
                }
            }
        }
        __syncwarp();

        u64 hA[16], hB[16];
        bias_init(hA, hB, sh + OFF_B0, hf);
        gemv_pair(hA, hB, wl0, fp, 54);
        __syncwarp();
        relu_stage(hA, hB, fp, hf);
        __syncwarp();

        bias_init(hA, hB, sh + OFF_B1, hf);
        gemv_pair(hA, hB, wl1, fp, 64);
        __syncwarp();
        relu_stage(hA, hB, fp, hf);
        __syncwarp();

        bias_init(hA, hB, sh + OFF_B2, hf);
        gemv_pair(hA, hB, wl2, fp, 64);

        float pA0=0.f,pA1=0.f,pA2=0.f,pB0=0.f,pB1=0.f,pB2=0.f;
        #pragma unroll
        for (int k=0; k<16; k++){
            float a0,a1,b0v,b1v;
            f2unpack(hA[k], a0, a1);
            f2unpack(hB[k], b0v, b1v);
            a0 = fmaxf(a0,0.f); a1 = fmaxf(a1,0.f);
            b0v = fmaxf(b0v,0.f); b1v = fmaxf(b1v,0.f);
            int n0 = hf*32 + 2*k;
            float q00 = sh[OFF_W3 + n0*3 + 0];
            float q01 = sh[OFF_W3 + n0*3 + 1];
            float q02 = sh[OFF_W3 + n0*3 + 2];
            float q10 = sh[OFF_W3 + n0*3 + 3];
            float q11 = sh[OFF_W3 + n0*3 + 4];
            float q12 = sh[OFF_W3 + n0*3 + 5];
            pA0 = fmaf(a0,q00, fmaf(a1,q10, pA0));
            pA1 = fmaf(a0,q01, fmaf(a1,q11, pA1));
            pA2 = fmaf(a0,q02, fmaf(a1,q12, pA2));
            pB0 = fmaf(b0v,q00, fmaf(b1v,q10, pB0));
            pB1 = fmaf(b0v,q01, fmaf(b1v,q11, pB1));
            pB2 = fmaf(b0v,q02, fmaf(b1v,q12, pB2));
        }
        pA0 += __shfl_xor_sync(0xffffffffu, pA0, 1);
        pA1 += __shfl_xor_sync(0xffffffffu, pA1, 1);
        pA2 += __shfl_xor_sync(0xffffffffu, pA2, 1);
        pB0 += __shfl_xor_sync(0xffffffffu, pB0, 1);
        pB1 += __shfl_xor_sync(0xffffffffu, pB1, 1);
        pB2 += __shfl_xor_sync(0xffffffffu, pB2, 1);

        float c0s = (hf ? pB0 : pA0) + sh[OFF_B3+0];
        float c1s = (hf ? pB1 : pA1) + sh[OFF_B3+1];
        float c2s = (hf ? pB2 : pA2) + sh[OFF_B3+2];
        float col0 = 1.f / (1.f + expf(-c0s));
        float col1 = 1.f / (1.f + expf(-c1s));
        float col2 = 1.f / (1.f + expf(-c2s));
        if (valid){
            g_c0[e] = wgt * col0;
            g_c1[e] = wgt * col1;
            g_c2[e] = wgt * col2;
        }
    }
}

// ---------------------------------------------------------------------------
// Kernel 4: per-ray reduction + background. 8 warps/block, 1 warp per ray.
// ---------------------------------------------------------------------------
__global__ void __launch_bounds__(256) reduce_kernel(float* __restrict__ out)
{
    int wrp = threadIdx.x >> 5;
    int lane = threadIdx.x & 31;
    int ray = blockIdx.x*8 + wrp;
    int base = g_base[ray];
    int cnt  = g_base[ray+1] - base;
    float a0 = 0.f, a1 = 0.f, a2 = 0.f;
    for (int i=lane; i<cnt; i+=32){
        a0 += g_c0[base+i];
        a1 += g_c1[base+i];
        a2 += g_c2[base+i];
    }
    #pragma unroll
    for (int o=16; o; o>>=1){
        a0 += __shfl_down_sync(0xffffffffu, a0, o);
        a1 += __shfl_down_sync(0xffffffffu, a1, o);
        a2 += __shfl_down_sync(0xffffffffu, a2, o);
    }
    if (lane == 0){
        float Tf = g_T[ray];
        out[ray*3+0] = a0 + Tf;
        out[ray*3+1] = a1 + Tf;
        out[ray*3+2] = a2 + Tf;
    }
}

extern "C" void kernel_launch(void* const* d_in, const int* in_sizes, int n_in,
                              void* d_out, int out_size)
{
    (void)in_sizes; (void)n_in; (void)out_size;
    const float* ro    = (const float*)d_in[0];
    const float* rd    = (const float*)d_in[1];
    const float* vd    = (const float*)d_in[2];
    const float* grid  = (const float*)d_in[3];
    const float* sobel = (const float*)d_in[4];
    const float* w0 = (const float*)d_in[5];
    const float* b0 = (const float*)d_in[6];
    const float* w1 = (const float*)d_in[7];
    const float* b1 = (const float*)d_in[8];
    const float* w2 = (const float*)d_in[9];
    const float* b2 = (const float*)d_in[10];
    const float* w3 = (const float*)d_in[11];
    const float* b3 = (const float*)d_in[12];
    float* out = (float*)d_out;

    fused_kernel<<<CONV_BLOCKS + NRAYS, 256>>>(grid, sobel, ro, rd);
    scan_kernel<<<1, 1024>>>();

    static int smem_set = 0;
    if (!smem_set){
        cudaFuncSetAttribute(mlp_kernel,
                             cudaFuncAttributeMaxDynamicSharedMemorySize, SMEM_MLP);
        smem_set = 1;
    }
    mlp_kernel<<<MLP_BLOCKS, MLP_NTH, SMEM_MLP>>>(ro, rd, vd, grid,
                                                  w0, b0, w1, b1, w2, b2, w3, b3);
    reduce_kernel<<<NRAYS/8, 256>>>(out);
}